// round 11
// baseline (speedup 1.0000x reference)
#include <cuda_runtime.h>
#include <stdint.h>

// TwoHotEmbedding: out[t,:] = w[i1[t],:]              if i1[t]==i2[t]
//                             w[i1[t],:] + w[i2[t],:]  otherwise
// B*S = 65536 tokens, D = 256 floats per row (1024 B = 32 lanes x 32 B).
//
// Converged model (R1-R10): kernel pinned at the path-independent chip LTS
// cap (~200 MB SM<->L2 crossing @ ~8.3 TB/s). Best kernel body = R10:
// one-shot 2 tokens/warp, 4 independent 256-bit evict_last gathers,
// FMA-mask epilogue (e1 + m*e2, m in {0,1}), single 256-bit store per
// token per lane -> kernel 24.10us (best measured).
// R11 delta: restore .cs (evict-first streaming) on the v8 stores — the
// small e2e-gap runs all used .cs; hypothesis is plain stores leave 67MB
// dirty in L2 whose writeback bleeds into the next graph replay.

struct V8 { float v[8]; };

__device__ __forceinline__ V8 ldg256_keep(const float* p) {
    V8 r;
    asm volatile(
        "ld.global.nc.L2::evict_last.v8.b32 {%0,%1,%2,%3,%4,%5,%6,%7}, [%8];"
        : "=f"(r.v[0]), "=f"(r.v[1]), "=f"(r.v[2]), "=f"(r.v[3]),
          "=f"(r.v[4]), "=f"(r.v[5]), "=f"(r.v[6]), "=f"(r.v[7])
        : "l"(p));
    return r;
}

__device__ __forceinline__ void stg256_stream(float* p, const float* r) {
    asm volatile(
        "st.global.cs.v8.b32 [%0], {%1,%2,%3,%4,%5,%6,%7,%8};"
        :: "l"(p),
           "f"(r[0]), "f"(r[1]), "f"(r[2]), "f"(r[3]),
           "f"(r[4]), "f"(r[5]), "f"(r[6]), "f"(r[7])
        : "memory");
}

__global__ __launch_bounds__(256) void twohot_kernel(
    const int* __restrict__ idx1,
    const int* __restrict__ idx2,
    const float* __restrict__ weight,   // [NUM_EMB, 256] f32
    float* __restrict__ out,            // [tokens, 256] f32
    int n_tokens)
{
    const int warp_global = (blockIdx.x * blockDim.x + threadIdx.x) >> 5;
    const int lane = threadIdx.x & 31;
    const int t0 = warp_global * 2;            // first of 2 tokens
    if (t0 >= n_tokens) return;

    // Paired index loads (64-bit each, warp-broadcast).
    const int2 ia = *(const int2*)(idx1 + t0);
    const int2 ib = *(const int2*)(idx2 + t0);

    const int off = lane * 8;
    const float* p1a = weight + (size_t)ia.x * 256 + off;
    const float* p2a = weight + (size_t)ib.x * 256 + off;
    const float* p1b = weight + (size_t)ia.y * 256 + off;
    const float* p2b = weight + (size_t)ib.y * 256 + off;

    // 4 independent 256-bit gathers in flight.
    V8 e1a = ldg256_keep(p1a);
    V8 e2a = ldg256_keep(p2a);
    V8 e1b = ldg256_keep(p1b);
    V8 e2b = ldg256_keep(p2b);

    // i1==i2 (prob ~1e-5): fold the condition into an FMA multiplier.
    const float ma = (ia.x == ib.x) ? 0.0f : 1.0f;
    const float mb = (ia.y == ib.y) ? 0.0f : 1.0f;

    float ra[8], rb[8];
    #pragma unroll
    for (int i = 0; i < 8; i++) {
        ra[i] = fmaf(ma, e2a.v[i], e1a.v[i]);
        rb[i] = fmaf(mb, e2b.v[i], e1b.v[i]);
    }

    float* oa = out + (size_t)t0 * 256 + off;
    stg256_stream(oa,       ra);
    stg256_stream(oa + 256, rb);
}

extern "C" void kernel_launch(void* const* d_in, const int* in_sizes, int n_in,
                              void* d_out, int out_size)
{
    const int* idx1 = (const int*)d_in[0];        // input_one [B,S] int32
    const int* idx2 = (const int*)d_in[1];        // input_two [B,S] int32
    const float* weight = (const float*)d_in[2];  // weight [100000,256] f32

    float* out = (float*)d_out;

    const int n_tokens = in_sizes[0];             // 65536
    (void)n_in; (void)out_size;

    // 8 warps/block, 2 tokens/warp -> 16 tokens per block -> 4096 blocks.
    const int tokens_per_block = 16;
    const int blocks = (n_tokens + tokens_per_block - 1) / tokens_per_block;
    twohot_kernel<<<blocks, 256>>>(idx1, idx2, weight, out, n_tokens);
}